// round 10
// baseline (speedup 1.0000x reference)
#include <cuda_runtime.h>
#include <cuda_fp16.h>
#include <math.h>
#include <stdint.h>

#define B_ 4
#define S_ 2048
#define D_ 1024
#define F_ 4096

// ---------------- scratch (static device globals; no allocs) ----------------
__device__ __half g_scores[(size_t)B_ * S_ * S_];   // 32 MB fp16
__device__ __half g_probs [(size_t)B_ * S_ * S_];   // 32 MB fp16
__device__ float  g_attn  [(size_t)B_ * S_ * D_];   // 32 MB
__device__ float  g_h1    [(size_t)B_ * S_ * D_];   // 32 MB fp32 residual
__device__ __half g_h1h   [(size_t)B_ * S_ * D_];   // 16 MB fp16 twin
__device__ __half g_f1    [(size_t)B_ * S_ * F_];   // 64 MB fp16
__device__ float  g_f2    [(size_t)B_ * S_ * D_];   // 32 MB
__device__ __half g_hh    [(size_t)B_ * S_ * D_];   // 16 MB h as fp16
__device__ __half g_hT    [(size_t)B_ * D_ * S_];   // 16 MB h^T fp16
__device__ __half g_w1T   [(size_t)F_ * D_];        // 8 MB
__device__ __half g_w2T   [(size_t)D_ * F_];        // 8 MB

// ---------------- helpers ----------------
__device__ __forceinline__ uint32_t smem_u32(const void* p) {
    return (uint32_t)__cvta_generic_to_shared(p);
}

#define CP_ASYNC16(sa, ga) \
    asm volatile("cp.async.cg.shared.global [%0], [%1], 16;" :: "r"(sa), "l"(ga))
#define CP_COMMIT() asm volatile("cp.async.commit_group;" ::: "memory")
#define CP_WAIT2()  asm volatile("cp.async.wait_group 2;" ::: "memory")

#define LDMATRIX_X4(r0, r1, r2, r3, addr)                                    \
    asm volatile("ldmatrix.sync.aligned.m8n8.x4.shared.b16 {%0,%1,%2,%3}, [%4];" \
                 : "=r"(r0), "=r"(r1), "=r"(r2), "=r"(r3) : "r"(addr))

__device__ __forceinline__ void mma_f16(float* d, const uint32_t* a, const uint32_t* b) {
    asm volatile(
        "mma.sync.aligned.m16n8k16.row.col.f32.f16.f16.f32 "
        "{%0,%1,%2,%3}, {%4,%5,%6,%7}, {%8,%9}, {%0,%1,%2,%3};"
        : "+f"(d[0]), "+f"(d[1]), "+f"(d[2]), "+f"(d[3])
        : "r"(a[0]), "r"(a[1]), "r"(a[2]), "r"(a[3]), "r"(b[0]), "r"(b[1]));
}

#define KC 32
#define ROW_BYTES 80

// ================= WIDE GEMM: CTA tile 128(M) x 256(N), 256 threads =========
// 8 warps (2m x 4n) of 64x64. 4-stage cp.async ring, 1 CTA/SM (123 KB smem).
#define A_TB_W (128 * ROW_BYTES)              // 10240
#define B_TB_W (256 * ROW_BYTES)              // 20480
#define STG_W  (A_TB_W + B_TB_W)              // 30720
#define NSTG_W 4
#define DYN_W  (NSTG_W * STG_W)               // 122880

__device__ __forceinline__ void load_tile_w(uint32_t sbase, const __half* __restrict__ Arow,
                                            const __half* __restrict__ Brow,
                                            int K, int kc, int tid) {
    const int r0 = tid >> 2;            // 0..63
    const int c  = tid & 3;
    const __half* Ap = Arow + (size_t)kc * KC + c * 8;
    const __half* Bp = Brow + (size_t)kc * KC + c * 8;
#pragma unroll
    for (int i = 0; i < 2; i++) {       // A: 128 rows
        int r = r0 + i * 64;
        CP_ASYNC16(sbase + r * ROW_BYTES + c * 16, Ap + (size_t)r * K);
    }
    uint32_t bb = sbase + A_TB_W;
#pragma unroll
    for (int i = 0; i < 4; i++) {       // B: 256 rows
        int r = r0 + i * 64;
        CP_ASYNC16(bb + r * ROW_BYTES + c * 16, Bp + (size_t)r * K);
    }
}

template <int EPI, typename OutT>
__global__ __launch_bounds__(256, 1)
void mma_gemm(const __half* __restrict__ A, const __half* __restrict__ Bm,
              const float* __restrict__ bias, OutT* __restrict__ C,
              int M, int N, int K, size_t sA, size_t sB, size_t sC, float alpha) {
    extern __shared__ char dsm[];
    const int tid = threadIdx.x, wid = tid >> 5, lane = tid & 31;
    const int z = blockIdx.z;
    A  += (size_t)z * sA;
    Bm += (size_t)z * sB;
    C  += (size_t)z * sC;
    const int m0 = blockIdx.y * 128;
    const int n0 = blockIdx.x * 256;
    const __half* Arow = A + (size_t)m0 * K;
    const __half* Brow = Bm + (size_t)n0 * K;
    const int NC = K / KC;

    const int wm = (wid & 1) * 64;        // 2 m-warps
    const int wn = (wid >> 1) * 64;       // 4 n-warps
    const int gq = lane >> 2;
    const int tg = lane & 3;

    float acc[4][8][4];
#pragma unroll
    for (int g = 0; g < 4; g++)
#pragma unroll
        for (int j = 0; j < 8; j++)
#pragma unroll
            for (int q = 0; q < 4; q++) acc[g][j][q] = 0.0f;

    const uint32_t s0 = smem_u32(dsm);
    const uint32_t a_off = (uint32_t)(wm + (lane & 15)) * ROW_BYTES + ((lane >> 4) & 1) * 16;
    const uint32_t b_off = A_TB_W +
        (uint32_t)(wn + (lane & 7) + ((lane >> 4) & 1) * 8) * ROW_BYTES + ((lane >> 3) & 1) * 16;

#pragma unroll
    for (int s = 0; s < NSTG_W - 1; s++) {
        load_tile_w(s0 + s * STG_W, Arow, Brow, K, s, tid);
        CP_COMMIT();
    }
    for (int k = 0; k < NC; k++) {
        const int buf = k & (NSTG_W - 1);
        CP_WAIT2();
        __syncthreads();
        if (k + NSTG_W - 1 < NC)
            load_tile_w(s0 + ((k + NSTG_W - 1) & (NSTG_W - 1)) * STG_W,
                        Arow, Brow, K, k + NSTG_W - 1, tid);
        CP_COMMIT();

        const uint32_t sb = s0 + buf * STG_W;
        const uint32_t aab = sb + a_off;
        const uint32_t bab = sb + b_off;
#pragma unroll
        for (int ks = 0; ks < 2; ks++) {
            const uint32_t kbb = ks * 32;
            uint32_t afr[4][4];
#pragma unroll
            for (int g = 0; g < 4; g++)
                LDMATRIX_X4(afr[g][0], afr[g][1], afr[g][2], afr[g][3],
                            aab + g * (16 * ROW_BYTES) + kbb);
            uint32_t bfr[8][2];
#pragma unroll
            for (int p = 0; p < 4; p++) {
                uint32_t t0, t1, t2, t3;
                LDMATRIX_X4(t0, t1, t2, t3, bab + p * (16 * ROW_BYTES) + kbb);
                bfr[2 * p][0] = t0; bfr[2 * p][1] = t1;
                bfr[2 * p + 1][0] = t2; bfr[2 * p + 1][1] = t3;
            }
#pragma unroll
            for (int g = 0; g < 4; g++)
#pragma unroll
                for (int j = 0; j < 8; j++) mma_f16(acc[g][j], afr[g], bfr[j]);
        }
    }

#pragma unroll
    for (int g = 0; g < 4; g++) {
        const int rb = m0 + wm + g * 16 + gq;
#pragma unroll
        for (int j = 0; j < 8; j++) {
            const int cb = n0 + wn + j * 8 + tg * 2;
            float bx = 0.f, by = 0.f;
            if (EPI != 0) { bx = bias[cb]; by = bias[cb + 1]; }
#pragma unroll
            for (int hh = 0; hh < 2; hh++) {
                float x = acc[g][j][hh * 2 + 0];
                float y = acc[g][j][hh * 2 + 1];
                if (EPI == 0) {
                    x *= alpha; y *= alpha;
                } else {
                    x += bx; y += by;
                    if (EPI == 1) {
                        x = 0.5f * x * (1.0f + erff(x * 0.7071067811865475f));
                        y = 0.5f * y * (1.0f + erff(y * 0.7071067811865475f));
                    }
                }
                OutT* cp = C + (size_t)(rb + hh * 8) * N + cb;
                if (sizeof(OutT) == 2) {
                    *(__half2*)cp = __floats2half2_rn(x, y);
                } else {
                    *(float2*)cp = make_float2(x, y);
                }
            }
        }
    }
}

// ================= symmetric scores GEMM (128x128, 128 threads) =============
#define T_TILE_BYTES (128 * ROW_BYTES)        // 10240
#define STAGE_BYTES (2 * T_TILE_BYTES)        // 20480
#define NSTAGE 4
#define DYN_SMEM (NSTAGE * STAGE_BYTES)       // 81920 -> 2 CTAs/SM

__device__ __forceinline__ void load_tile(uint32_t sbase, const __half* __restrict__ Arow,
                                          const __half* __restrict__ Brow,
                                          int K, int kc, int tid) {
    const int r0 = tid >> 2;
    const int c  = tid & 3;
    const __half* Ap = Arow + (size_t)kc * KC + c * 8;
    const __half* Bp = Brow + (size_t)kc * KC + c * 8;
#pragma unroll
    for (int i = 0; i < 4; i++) {
        int r = r0 + i * 32;
        CP_ASYNC16(sbase + r * ROW_BYTES + c * 16, Ap + (size_t)r * K);
    }
    uint32_t bb = sbase + T_TILE_BYTES;
#pragma unroll
    for (int i = 0; i < 4; i++) {
        int r = r0 + i * 32;
        CP_ASYNC16(bb + r * ROW_BYTES + c * 16, Bp + (size_t)r * K);
    }
}

__device__ __forceinline__ void gemm_mainloop(char* dsm, const __half* Arow,
                                              const __half* Brow, int K, int tid,
                                              int wm, int wn, float acc[4][8][4]) {
    const uint32_t s0 = smem_u32(dsm);
    const int lane = tid & 31;
    const uint32_t a_off = (uint32_t)(wm + (lane & 15)) * ROW_BYTES + ((lane >> 4) & 1) * 16;
    const uint32_t b_off = T_TILE_BYTES +
        (uint32_t)(wn + (lane & 7) + ((lane >> 4) & 1) * 8) * ROW_BYTES + ((lane >> 3) & 1) * 16;
    const int NC = K / KC;

#pragma unroll
    for (int s = 0; s < NSTAGE - 1; s++) {
        load_tile(s0 + s * STAGE_BYTES, Arow, Brow, K, s, tid);
        CP_COMMIT();
    }
    for (int k = 0; k < NC; k++) {
        const int buf = k & (NSTAGE - 1);
        CP_WAIT2();
        __syncthreads();
        if (k + NSTAGE - 1 < NC)
            load_tile(s0 + ((k + NSTAGE - 1) & (NSTAGE - 1)) * STAGE_BYTES,
                      Arow, Brow, K, k + NSTAGE - 1, tid);
        CP_COMMIT();

        const uint32_t sb = s0 + buf * STAGE_BYTES;
        const uint32_t aab = sb + a_off;
        const uint32_t bab = sb + b_off;
#pragma unroll
        for (int ks = 0; ks < 2; ks++) {
            const uint32_t kbb = ks * 32;
            uint32_t afr[4][4];
#pragma unroll
            for (int g = 0; g < 4; g++)
                LDMATRIX_X4(afr[g][0], afr[g][1], afr[g][2], afr[g][3],
                            aab + g * (16 * ROW_BYTES) + kbb);
            uint32_t bfr[8][2];
#pragma unroll
            for (int p = 0; p < 4; p++) {
                uint32_t t0, t1, t2, t3;
                LDMATRIX_X4(t0, t1, t2, t3, bab + p * (16 * ROW_BYTES) + kbb);
                bfr[2 * p][0] = t0; bfr[2 * p][1] = t1;
                bfr[2 * p + 1][0] = t2; bfr[2 * p + 1][1] = t3;
            }
#pragma unroll
            for (int g = 0; g < 4; g++)
#pragma unroll
                for (int j = 0; j < 8; j++) mma_f16(acc[g][j], afr[g], bfr[j]);
        }
    }
}

#define NT (S_ / 128)
#define NTRI (NT * (NT + 1) / 2)   // 136
#define TP 136

__global__ __launch_bounds__(128, 2)
void mma_gemm_sym(const __half* __restrict__ A, __half* __restrict__ C,
                  int K, size_t sA, size_t sC, float alpha) {
    extern __shared__ char dsm[];
    const int tid = threadIdx.x, wid = tid >> 5, lane = tid & 31;
    const int z = blockIdx.z;
    A += (size_t)z * sA;
    C += (size_t)z * sC;

    int ti = blockIdx.x, i = 0;
    while (ti >= NT - i) { ti -= NT - i; i++; }
    const int j = i + ti;
    const int m0 = i * 128, n0 = j * 128;

    const int wm = (wid & 1) * 64;
    const int wn = (wid >> 1) * 64;
    const int gq = lane >> 2;
    const int tg = lane & 3;

    float acc[4][8][4];
#pragma unroll
    for (int g = 0; g < 4; g++)
#pragma unroll
        for (int jj = 0; jj < 8; jj++)
#pragma unroll
            for (int q = 0; q < 4; q++) acc[g][jj][q] = 0.0f;

    gemm_mainloop(dsm, A + (size_t)m0 * K, A + (size_t)n0 * K, K, tid, wm, wn, acc);

    __half (*T)[TP] = (__half (*)[TP])dsm;
    __syncthreads();
#pragma unroll
    for (int g = 0; g < 4; g++) {
        const int rl = wm + g * 16 + gq;
#pragma unroll
        for (int jj = 0; jj < 8; jj++) {
            const int cl = wn + jj * 8 + tg * 2;
#pragma unroll
            for (int hh = 0; hh < 2; hh++) {
                __half2 hv = __floats2half2_rn(acc[g][jj][hh * 2] * alpha,
                                               acc[g][jj][hh * 2 + 1] * alpha);
                *(__half2*)&T[rl + hh * 8][cl] = hv;
            }
        }
    }
    __syncthreads();

    for (int it = 0; it < 16; it++) {
        int id = tid + it * 128;
        int r = id >> 4, c8 = (id & 15) * 8;
        *(uint4*)(C + (size_t)(m0 + r) * S_ + n0 + c8) = *(uint4*)&T[r][c8];
    }
    if (i != j) {
        for (int it = 0; it < 16; it++) {
            int id = tid + it * 128;
            int mr = id >> 4, mc8 = (id & 15) * 8;
            __half v[8];
#pragma unroll
            for (int q = 0; q < 8; q++) v[q] = T[mc8 + q][mr];
            *(uint4*)(C + (size_t)(n0 + mr) * S_ + m0 + mc8) = *(uint4*)v;
        }
    }
}

// ---------------- pointwise / reduction kernels ----------------
__device__ __forceinline__ float warpSum(float v) {
#pragma unroll
    for (int o = 16; o > 0; o >>= 1) v += __shfl_xor_sync(0xFFFFFFFFu, v, o);
    return v;
}
__device__ __forceinline__ float warpMax(float v) {
#pragma unroll
    for (int o = 16; o > 0; o >>= 1) v = fmaxf(v, __shfl_xor_sync(0xFFFFFFFFu, v, o));
    return v;
}
__device__ __forceinline__ float blockSum(float v) {
    __shared__ float sh[9];
    __syncthreads();
    int lane = threadIdx.x & 31, w = threadIdx.x >> 5;
    v = warpSum(v);
    if (lane == 0) sh[w] = v;
    __syncthreads();
    if (w == 0) {
        float x = (lane < 8) ? sh[lane] : 0.0f;
        x = warpSum(x);
        if (lane == 0) sh[8] = x;
    }
    __syncthreads();
    return sh[8];
}
__device__ __forceinline__ float blockMax(float v) {
    __shared__ float sh[9];
    __syncthreads();
    int lane = threadIdx.x & 31, w = threadIdx.x >> 5;
    v = warpMax(v);
    if (lane == 0) sh[w] = v;
    __syncthreads();
    if (w == 0) {
        float x = (lane < 8) ? sh[lane] : -INFINITY;
        x = warpMax(x);
        if (lane == 0) sh[8] = x;
    }
    __syncthreads();
    return sh[8];
}

__global__ __launch_bounds__(256)
void softmax_kernel(const __half* __restrict__ scores, const float* __restrict__ mask,
                    __half* __restrict__ probs) {
    const int row = blockIdx.x;
    const int b = row / S_;
    const __half* p = scores + (size_t)row * S_;
    __half* po = probs + (size_t)row * S_;
    const float* mk = mask + (size_t)b * S_;
    const int t = threadIdx.x;
    float v[8];
    float mx = -INFINITY;
#pragma unroll
    for (int i = 0; i < 8; i++) {
        int k = t + i * 256;
        v[i] = __half2float(p[k]) + mk[k];
        mx = fmaxf(mx, v[i]);
    }
    mx = blockMax(mx);
    float s = 0.0f;
#pragma unroll
    for (int i = 0; i < 8; i++) {
        v[i] = __expf(v[i] - mx);
        s += v[i];
    }
    s = blockSum(s);
    float inv = 1.0f / s;
#pragma unroll
    for (int i = 0; i < 8; i++) po[t + i * 256] = __float2half_rn(v[i] * inv);
}

__global__ __launch_bounds__(256)
void add_ln_kernel(const float* __restrict__ x, const float* __restrict__ res,
                   const float* __restrict__ gamma, const float* __restrict__ beta,
                   float* __restrict__ out, __half* __restrict__ out_h) {
    const int row = blockIdx.x;
    const float* px = x + (size_t)row * D_;
    const float* pr = res + (size_t)row * D_;
    float* po = out + (size_t)row * D_;
    const int t = threadIdx.x;
    float v[4];
    float s = 0.0f, s2 = 0.0f;
#pragma unroll
    for (int i = 0; i < 4; i++) {
        int k = t + i * 256;
        v[i] = px[k] + pr[k];
        s += v[i];
        s2 += v[i] * v[i];
    }
    s = blockSum(s);
    s2 = blockSum(s2);
    const float mu = s * (1.0f / D_);
    const float var = s2 * (1.0f / D_) - mu * mu;
    const float inv = rsqrtf(var + 1e-5f);
#pragma unroll
    for (int i = 0; i < 4; i++) {
        int k = t + i * 256;
        float y = (v[i] - mu) * inv * gamma[k] + beta[k];
        po[k] = y;
        if (out_h) out_h[(size_t)row * D_ + k] = __float2half_rn(y);
    }
}

__global__ __launch_bounds__(256)
void conv_and_transpose_kernel(const float* __restrict__ src, __half* __restrict__ dst,
                               __half* __restrict__ dstT, int R, int C,
                               size_t sS, size_t sD, size_t sDT) {
    __shared__ float t[32][33];
    src  += (size_t)blockIdx.z * sS;
    if (dst) dst += (size_t)blockIdx.z * sD;
    dstT += (size_t)blockIdx.z * sDT;
    const int c0 = blockIdx.x * 32, r0 = blockIdx.y * 32;
    const int x = threadIdx.x & 31, y = (threadIdx.x >> 5) * 4;
#pragma unroll
    for (int i = 0; i < 4; i++) {
        float v = src[(size_t)(r0 + y + i) * C + c0 + x];
        t[y + i][x] = v;
        if (dst) dst[(size_t)(r0 + y + i) * C + c0 + x] = __float2half_rn(v);
    }
    __syncthreads();
#pragma unroll
    for (int i = 0; i < 4; i++)
        dstT[(size_t)(c0 + y + i) * R + r0 + x] = __float2half_rn(t[x][y + i]);
}

// ---------------- launch ----------------
extern "C" void kernel_launch(void* const* d_in, const int* in_sizes, int n_in,
                              void* d_out, int out_size) {
    const float* h    = (const float*)d_in[0];
    const float* mask = (const float*)d_in[1];
    const float* w1   = (const float*)d_in[2];
    const float* b1   = (const float*)d_in[3];
    const float* w2   = (const float*)d_in[4];
    const float* b2   = (const float*)d_in[5];
    const float* g1   = (const float*)d_in[6];
    const float* be1  = (const float*)d_in[7];
    const float* g2   = (const float*)d_in[8];
    const float* be2  = (const float*)d_in[9];
    float* out = (float*)d_out;

    float *attn, *h1, *f2;
    __half *scores, *probs, *h1h, *f1, *hh, *hT, *w1T, *w2T;
    cudaGetSymbolAddress((void**)&scores, g_scores);
    cudaGetSymbolAddress((void**)&probs, g_probs);
    cudaGetSymbolAddress((void**)&attn, g_attn);
    cudaGetSymbolAddress((void**)&h1, g_h1);
    cudaGetSymbolAddress((void**)&h1h, g_h1h);
    cudaGetSymbolAddress((void**)&f1, g_f1);
    cudaGetSymbolAddress((void**)&f2, g_f2);
    cudaGetSymbolAddress((void**)&hh, g_hh);
    cudaGetSymbolAddress((void**)&hT, g_hT);
    cudaGetSymbolAddress((void**)&w1T, g_w1T);
    cudaGetSymbolAddress((void**)&w2T, g_w2T);

    cudaFuncSetAttribute(mma_gemm_sym,        cudaFuncAttributeMaxDynamicSharedMemorySize, DYN_SMEM);
    cudaFuncSetAttribute(mma_gemm<0, float>,  cudaFuncAttributeMaxDynamicSharedMemorySize, DYN_W);
    cudaFuncSetAttribute(mma_gemm<1, __half>, cudaFuncAttributeMaxDynamicSharedMemorySize, DYN_W);
    cudaFuncSetAttribute(mma_gemm<2, float>,  cudaFuncAttributeMaxDynamicSharedMemorySize, DYN_W);

    const size_t SD = (size_t)S_ * D_;
    const size_t SS = (size_t)S_ * S_;

    // operand prep
    conv_and_transpose_kernel<<<dim3(D_ / 32, S_ / 32, B_), 256>>>(
        h, hh, hT, S_, D_, SD, SD, SD);
    conv_and_transpose_kernel<<<dim3(F_ / 32, D_ / 32, 1), 256>>>(
        w1, nullptr, w1T, D_, F_, 0, 0, 0);
    conv_and_transpose_kernel<<<dim3(D_ / 32, F_ / 32, 1), 256>>>(
        w2, nullptr, w2T, F_, D_, 0, 0, 0);

    // 1) scores = (h @ h^T) / 32  (symmetric, fp16)
    mma_gemm_sym<<<dim3(NTRI, 1, B_), 128, DYN_SMEM>>>(
        hh, scores, D_, SD, SS, 0.03125f);

    // 2) softmax (+mask) -> fp16 probs
    softmax_kernel<<<B_ * S_, 256>>>(scores, mask, probs);

    // 3) attn = P @ h   (wide tiles: N-tile 256)
    mma_gemm<0, float><<<dim3(D_ / 256, S_ / 128, B_), 256, DYN_W>>>(
        probs, hT, nullptr, attn, S_, D_, S_, SS, SD, SD, 1.0f);

    // 4) h1 = LN1(h + attn)
    add_ln_kernel<<<B_ * S_, 256>>>(attn, h, g1, be1, h1, h1h);

    // 5) f1 = GELU(h1 @ w1 + b1)
    mma_gemm<1, __half><<<dim3(F_ / 256, (B_ * S_) / 128, 1), 256, DYN_W>>>(
        h1h, w1T, b1, f1, B_ * S_, F_, D_, 0, 0, 0, 1.0f);

    // 6) f2 = f1 @ w2 + b2
    mma_gemm<2, float><<<dim3(D_ / 256, (B_ * S_) / 128, 1), 256, DYN_W>>>(
        f1, w2T, b2, f2, B_ * S_, D_, F_, 0, 0, 0, 1.0f);

    // 7) out = LN2(h1 + f2)
    add_ln_kernel<<<B_ * S_, 256>>>(f2, h1, g2, be2, out, nullptr);
}

// round 14
// speedup vs baseline: 1.1293x; 1.1293x over previous
#include <cuda_runtime.h>
#include <cuda_fp16.h>
#include <math.h>
#include <stdint.h>

#define B_ 4
#define S_ 2048
#define D_ 1024
#define F_ 4096

// ---------------- scratch (static device globals; no allocs) ----------------
__device__ __half g_scores[(size_t)B_ * S_ * S_];   // 32 MB fp16
__device__ __half g_probs [(size_t)B_ * S_ * S_];   // 32 MB fp16
__device__ float  g_attn  [(size_t)B_ * S_ * D_];   // 32 MB
__device__ float  g_h1    [(size_t)B_ * S_ * D_];   // 32 MB fp32 residual
__device__ __half g_h1h   [(size_t)B_ * S_ * D_];   // 16 MB fp16 twin
__device__ __half g_f1    [(size_t)B_ * S_ * F_];   // 64 MB fp16
__device__ float  g_f2    [(size_t)B_ * S_ * D_];   // 32 MB
__device__ __half g_hh    [(size_t)B_ * S_ * D_];   // 16 MB h as fp16
__device__ __half g_hT    [(size_t)B_ * D_ * S_];   // 16 MB h^T fp16
__device__ __half g_w1T   [(size_t)F_ * D_];        // 8 MB
__device__ __half g_w2T   [(size_t)D_ * F_];        // 8 MB

// ---------------- helpers ----------------
__device__ __forceinline__ uint32_t smem_u32(const void* p) {
    return (uint32_t)__cvta_generic_to_shared(p);
}

#define CP_ASYNC16(sa, ga) \
    asm volatile("cp.async.cg.shared.global [%0], [%1], 16;" :: "r"(sa), "l"(ga))
#define CP_COMMIT() asm volatile("cp.async.commit_group;" ::: "memory")
#define CP_WAIT1()  asm volatile("cp.async.wait_group 1;" ::: "memory")

#define LDMATRIX_X4(r0, r1, r2, r3, addr)                                    \
    asm volatile("ldmatrix.sync.aligned.m8n8.x4.shared.b16 {%0,%1,%2,%3}, [%4];" \
                 : "=r"(r0), "=r"(r1), "=r"(r2), "=r"(r3) : "r"(addr))

__device__ __forceinline__ void mma_f16(float* d, const uint32_t* a, const uint32_t* b) {
    asm volatile(
        "mma.sync.aligned.m16n8k16.row.col.f32.f16.f16.f32 "
        "{%0,%1,%2,%3}, {%4,%5,%6,%7}, {%8,%9}, {%0,%1,%2,%3};"
        : "+f"(d[0]), "+f"(d[1]), "+f"(d[2]), "+f"(d[3])
        : "r"(a[0]), "r"(a[1]), "r"(a[2]), "r"(a[3]), "r"(b[0]), "r"(b[1]));
}

// ---------------- GEMM geometry: CTA 128x128, KC=64 halfs ----------------
// SMEM row = 64 halfs (128 B data) + 16 B pad -> pitch 144 B.
// ldmatrix bank check: row r base = 36r u32 = 4r mod 32 banks; 8 rows x 4 banks
// each -> fully disjoint -> conflict-free.
#define KC 64
#define ROW_BYTES 144
#define T_TILE_BYTES (128 * ROW_BYTES)        // 18432
#define STAGE_BYTES (2 * T_TILE_BYTES)        // 36864 (A + B)
#define NSTAGE 3
#define DYN_SMEM (NSTAGE * STAGE_BYTES)       // 110592 -> 2 CTAs = 221 KB/SM

__device__ __forceinline__ void load_tile(uint32_t sbase, const __half* __restrict__ Arow,
                                          const __half* __restrict__ Brow,
                                          int K, int kc, int tid) {
    const int r0 = tid >> 3;            // 0..15
    const int c  = tid & 7;             // 16B chunk (8 halfs), 0..7
    const __half* Ap = Arow + (size_t)kc * KC + c * 8;
    const __half* Bp = Brow + (size_t)kc * KC + c * 8;
#pragma unroll
    for (int i = 0; i < 8; i++) {
        int r = r0 + i * 16;
        CP_ASYNC16(sbase + r * ROW_BYTES + c * 16, Ap + (size_t)r * K);
    }
    uint32_t bb = sbase + T_TILE_BYTES;
#pragma unroll
    for (int i = 0; i < 8; i++) {
        int r = r0 + i * 16;
        CP_ASYNC16(bb + r * ROW_BYTES + c * 16, Bp + (size_t)r * K);
    }
}

// Pipelined mainloop for one 128x128 tile; acc[4][8][4] accumulated.
__device__ __forceinline__ void gemm_mainloop(char* dsm, const __half* Arow,
                                              const __half* Brow, int K, int tid,
                                              int wm, int wn, float acc[4][8][4]) {
    const uint32_t s0 = smem_u32(dsm);
    const int lane = tid & 31;
    const uint32_t a_off = (uint32_t)(wm + (lane & 15)) * ROW_BYTES + ((lane >> 4) & 1) * 16;
    const uint32_t b_off = T_TILE_BYTES +
        (uint32_t)(wn + (lane & 7) + ((lane >> 4) & 1) * 8) * ROW_BYTES + ((lane >> 3) & 1) * 16;
    const int NC = K / KC;

#pragma unroll
    for (int s = 0; s < NSTAGE - 1; s++) {
        load_tile(s0 + s * STAGE_BYTES, Arow, Brow, K, s, tid);
        CP_COMMIT();
    }
    int buf = 0;
    for (int k = 0; k < NC; k++) {
        CP_WAIT1();          // pending {k, k+1} -> <=1 means chunk k resident
        __syncthreads();     // single barrier; also frees buffer consumed at k-1
        if (k + NSTAGE - 1 < NC) {
            int nb = buf + NSTAGE - 1;
            if (nb >= NSTAGE) nb -= NSTAGE;
            load_tile(s0 + nb * STAGE_BYTES, Arow, Brow, K, k + NSTAGE - 1, tid);
        }
        CP_COMMIT();

        const uint32_t sb = s0 + buf * STAGE_BYTES;
        const uint32_t aab = sb + a_off;
        const uint32_t bab = sb + b_off;
#pragma unroll
        for (int ks = 0; ks < 4; ks++) {      // four k16 steps per 64-half chunk
            const uint32_t kbb = ks * 32;     // 16 halfs = 32B
            uint32_t afr[4][4];
#pragma unroll
            for (int g = 0; g < 4; g++)
                LDMATRIX_X4(afr[g][0], afr[g][1], afr[g][2], afr[g][3],
                            aab + g * (16 * ROW_BYTES) + kbb);
            uint32_t bfr[8][2];
#pragma unroll
            for (int p = 0; p < 4; p++) {
                uint32_t t0, t1, t2, t3;
                LDMATRIX_X4(t0, t1, t2, t3, bab + p * (16 * ROW_BYTES) + kbb);
                bfr[2 * p][0] = t0; bfr[2 * p][1] = t1;
                bfr[2 * p + 1][0] = t2; bfr[2 * p + 1][1] = t3;
            }
#pragma unroll
            for (int g = 0; g < 4; g++)
#pragma unroll
                for (int j = 0; j < 8; j++) mma_f16(acc[g][j], afr[g], bfr[j]);
        }
        buf++;
        if (buf == NSTAGE) buf = 0;
    }
}

// ---------------- generic fp16 GEMM (EPI: 0=*alpha, 1=+bias GELU, 2=+bias) ----
template <int EPI, typename OutT>
__global__ __launch_bounds__(128, 2)
void mma_gemm(const __half* __restrict__ A, const __half* __restrict__ Bm,
              const float* __restrict__ bias, OutT* __restrict__ C,
              int M, int N, int K, size_t sA, size_t sB, size_t sC, float alpha) {
    extern __shared__ char dsm[];
    const int tid = threadIdx.x, wid = tid >> 5, lane = tid & 31;
    const int z = blockIdx.z;
    A  += (size_t)z * sA;
    Bm += (size_t)z * sB;
    C  += (size_t)z * sC;
    const int m0 = blockIdx.y * 128;
    const int n0 = blockIdx.x * 128;
    const int wm = (wid & 1) * 64;
    const int wn = (wid >> 1) * 64;
    const int gq = lane >> 2;
    const int tg = lane & 3;

    float acc[4][8][4];
#pragma unroll
    for (int g = 0; g < 4; g++)
#pragma unroll
        for (int j = 0; j < 8; j++)
#pragma unroll
            for (int q = 0; q < 4; q++) acc[g][j][q] = 0.0f;

    gemm_mainloop(dsm, A + (size_t)m0 * K, Bm + (size_t)n0 * K, K, tid, wm, wn, acc);

#pragma unroll
    for (int g = 0; g < 4; g++) {
        const int rb = m0 + wm + g * 16 + gq;
#pragma unroll
        for (int j = 0; j < 8; j++) {
            const int cb = n0 + wn + j * 8 + tg * 2;
            float bx = 0.f, by = 0.f;
            if (EPI != 0) { bx = bias[cb]; by = bias[cb + 1]; }
#pragma unroll
            for (int hh = 0; hh < 2; hh++) {
                float x = acc[g][j][hh * 2 + 0];
                float y = acc[g][j][hh * 2 + 1];
                if (EPI == 0) {
                    x *= alpha; y *= alpha;
                } else {
                    x += bx; y += by;
                    if (EPI == 1) {
                        x = 0.5f * x * (1.0f + erff(x * 0.7071067811865475f));
                        y = 0.5f * y * (1.0f + erff(y * 0.7071067811865475f));
                    }
                }
                OutT* cp = C + (size_t)(rb + hh * 8) * N + cb;
                if (sizeof(OutT) == 2) {
                    *(__half2*)cp = __floats2half2_rn(x, y);
                } else {
                    *(float2*)cp = make_float2(x, y);
                }
            }
        }
    }
}

// ---------------- symmetric scores GEMM: C = (A A^T) * alpha, fp16 out -------
#define NT (S_ / 128)
#define NTRI (NT * (NT + 1) / 2)   // 136
#define TP 136

__global__ __launch_bounds__(128, 2)
void mma_gemm_sym(const __half* __restrict__ A, __half* __restrict__ C,
                  int K, size_t sA, size_t sC, float alpha) {
    extern __shared__ char dsm[];
    const int tid = threadIdx.x, wid = tid >> 5, lane = tid & 31;
    const int z = blockIdx.z;
    A += (size_t)z * sA;
    C += (size_t)z * sC;

    int ti = blockIdx.x, i = 0;
    while (ti >= NT - i) { ti -= NT - i; i++; }
    const int j = i + ti;
    const int m0 = i * 128, n0 = j * 128;

    const int wm = (wid & 1) * 64;
    const int wn = (wid >> 1) * 64;
    const int gq = lane >> 2;
    const int tg = lane & 3;

    float acc[4][8][4];
#pragma unroll
    for (int g = 0; g < 4; g++)
#pragma unroll
        for (int jj = 0; jj < 8; jj++)
#pragma unroll
            for (int q = 0; q < 4; q++) acc[g][jj][q] = 0.0f;

    gemm_mainloop(dsm, A + (size_t)m0 * K, A + (size_t)n0 * K, K, tid, wm, wn, acc);

    __half (*T)[TP] = (__half (*)[TP])dsm;
    __syncthreads();
#pragma unroll
    for (int g = 0; g < 4; g++) {
        const int rl = wm + g * 16 + gq;
#pragma unroll
        for (int jj = 0; jj < 8; jj++) {
            const int cl = wn + jj * 8 + tg * 2;
#pragma unroll
            for (int hh = 0; hh < 2; hh++) {
                __half2 hv = __floats2half2_rn(acc[g][jj][hh * 2] * alpha,
                                               acc[g][jj][hh * 2 + 1] * alpha);
                *(__half2*)&T[rl + hh * 8][cl] = hv;
            }
        }
    }
    __syncthreads();

    for (int it = 0; it < 16; it++) {
        int id = tid + it * 128;
        int r = id >> 4, c8 = (id & 15) * 8;
        *(uint4*)(C + (size_t)(m0 + r) * S_ + n0 + c8) = *(uint4*)&T[r][c8];
    }
    if (i != j) {
        for (int it = 0; it < 16; it++) {
            int id = tid + it * 128;
            int mr = id >> 4, mc8 = (id & 15) * 8;
            __half v[8];
#pragma unroll
            for (int q = 0; q < 8; q++) v[q] = T[mc8 + q][mr];
            *(uint4*)(C + (size_t)(n0 + mr) * S_ + m0 + mc8) = *(uint4*)v;
        }
    }
}

// ---------------- pointwise / reduction kernels ----------------
__device__ __forceinline__ float warpSum(float v) {
#pragma unroll
    for (int o = 16; o > 0; o >>= 1) v += __shfl_xor_sync(0xFFFFFFFFu, v, o);
    return v;
}
__device__ __forceinline__ float warpMax(float v) {
#pragma unroll
    for (int o = 16; o > 0; o >>= 1) v = fmaxf(v, __shfl_xor_sync(0xFFFFFFFFu, v, o));
    return v;
}
__device__ __forceinline__ float blockSum(float v) {
    __shared__ float sh[9];
    __syncthreads();
    int lane = threadIdx.x & 31, w = threadIdx.x >> 5;
    v = warpSum(v);
    if (lane == 0) sh[w] = v;
    __syncthreads();
    if (w == 0) {
        float x = (lane < 8) ? sh[lane] : 0.0f;
        x = warpSum(x);
        if (lane == 0) sh[8] = x;
    }
    __syncthreads();
    return sh[8];
}
__device__ __forceinline__ float blockMax(float v) {
    __shared__ float sh[9];
    __syncthreads();
    int lane = threadIdx.x & 31, w = threadIdx.x >> 5;
    v = warpMax(v);
    if (lane == 0) sh[w] = v;
    __syncthreads();
    if (w == 0) {
        float x = (lane < 8) ? sh[lane] : -INFINITY;
        x = warpMax(x);
        if (lane == 0) sh[8] = x;
    }
    __syncthreads();
    return sh[8];
}

__global__ __launch_bounds__(256)
void softmax_kernel(const __half* __restrict__ scores, const float* __restrict__ mask,
                    __half* __restrict__ probs) {
    const int row = blockIdx.x;
    const int b = row / S_;
    const __half* p = scores + (size_t)row * S_;
    __half* po = probs + (size_t)row * S_;
    const float* mk = mask + (size_t)b * S_;
    const int t = threadIdx.x;
    float v[8];
    float mx = -INFINITY;
#pragma unroll
    for (int i = 0; i < 8; i++) {
        int k = t + i * 256;
        v[i] = __half2float(p[k]) + mk[k];
        mx = fmaxf(mx, v[i]);
    }
    mx = blockMax(mx);
    float s = 0.0f;
#pragma unroll
    for (int i = 0; i < 8; i++) {
        v[i] = __expf(v[i] - mx);
        s += v[i];
    }
    s = blockSum(s);
    float inv = 1.0f / s;
#pragma unroll
    for (int i = 0; i < 8; i++) po[t + i * 256] = __float2half_rn(v[i] * inv);
}

__global__ __launch_bounds__(256)
void add_ln_kernel(const float* __restrict__ x, const float* __restrict__ res,
                   const float* __restrict__ gamma, const float* __restrict__ beta,
                   float* __restrict__ out, __half* __restrict__ out_h) {
    const int row = blockIdx.x;
    const float* px = x + (size_t)row * D_;
    const float* pr = res + (size_t)row * D_;
    float* po = out + (size_t)row * D_;
    const int t = threadIdx.x;
    float v[4];
    float s = 0.0f, s2 = 0.0f;
#pragma unroll
    for (int i = 0; i < 4; i++) {
        int k = t + i * 256;
        v[i] = px[k] + pr[k];
        s += v[i];
        s2 += v[i] * v[i];
    }
    s = blockSum(s);
    s2 = blockSum(s2);
    const float mu = s * (1.0f / D_);
    const float var = s2 * (1.0f / D_) - mu * mu;
    const float inv = rsqrtf(var + 1e-5f);
#pragma unroll
    for (int i = 0; i < 4; i++) {
        int k = t + i * 256;
        float y = (v[i] - mu) * inv * gamma[k] + beta[k];
        po[k] = y;
        if (out_h) out_h[(size_t)row * D_ + k] = __float2half_rn(y);
    }
}

__global__ __launch_bounds__(256)
void conv_and_transpose_kernel(const float* __restrict__ src, __half* __restrict__ dst,
                               __half* __restrict__ dstT, int R, int C,
                               size_t sS, size_t sD, size_t sDT) {
    __shared__ float t[32][33];
    src  += (size_t)blockIdx.z * sS;
    if (dst) dst += (size_t)blockIdx.z * sD;
    dstT += (size_t)blockIdx.z * sDT;
    const int c0 = blockIdx.x * 32, r0 = blockIdx.y * 32;
    const int x = threadIdx.x & 31, y = (threadIdx.x >> 5) * 4;
#pragma unroll
    for (int i = 0; i < 4; i++) {
        float v = src[(size_t)(r0 + y + i) * C + c0 + x];
        t[y + i][x] = v;
        if (dst) dst[(size_t)(r0 + y + i) * C + c0 + x] = __float2half_rn(v);
    }
    __syncthreads();
#pragma unroll
    for (int i = 0; i < 4; i++)
        dstT[(size_t)(c0 + y + i) * R + r0 + x] = __float2half_rn(t[x][y + i]);
}

// ---------------- launch ----------------
extern "C" void kernel_launch(void* const* d_in, const int* in_sizes, int n_in,
                              void* d_out, int out_size) {
    const float* h    = (const float*)d_in[0];
    const float* mask = (const float*)d_in[1];
    const float* w1   = (const float*)d_in[2];
    const float* b1   = (const float*)d_in[3];
    const float* w2   = (const float*)d_in[4];
    const float* b2   = (const float*)d_in[5];
    const float* g1   = (const float*)d_in[6];
    const float* be1  = (const float*)d_in[7];
    const float* g2   = (const float*)d_in[8];
    const float* be2  = (const float*)d_in[9];
    float* out = (float*)d_out;

    float *attn, *h1, *f2;
    __half *scores, *probs, *h1h, *f1, *hh, *hT, *w1T, *w2T;
    cudaGetSymbolAddress((void**)&scores, g_scores);
    cudaGetSymbolAddress((void**)&probs, g_probs);
    cudaGetSymbolAddress((void**)&attn, g_attn);
    cudaGetSymbolAddress((void**)&h1, g_h1);
    cudaGetSymbolAddress((void**)&h1h, g_h1h);
    cudaGetSymbolAddress((void**)&f1, g_f1);
    cudaGetSymbolAddress((void**)&f2, g_f2);
    cudaGetSymbolAddress((void**)&hh, g_hh);
    cudaGetSymbolAddress((void**)&hT, g_hT);
    cudaGetSymbolAddress((void**)&w1T, g_w1T);
    cudaGetSymbolAddress((void**)&w2T, g_w2T);

    cudaFuncSetAttribute(mma_gemm_sym,        cudaFuncAttributeMaxDynamicSharedMemorySize, DYN_SMEM);
    cudaFuncSetAttribute(mma_gemm<0, float>,  cudaFuncAttributeMaxDynamicSharedMemorySize, DYN_SMEM);
    cudaFuncSetAttribute(mma_gemm<1, __half>, cudaFuncAttributeMaxDynamicSharedMemorySize, DYN_SMEM);
    cudaFuncSetAttribute(mma_gemm<2, float>,  cudaFuncAttributeMaxDynamicSharedMemorySize, DYN_SMEM);

    const size_t SD = (size_t)S_ * D_;
    const size_t SS = (size_t)S_ * S_;

    // operand prep
    conv_and_transpose_kernel<<<dim3(D_ / 32, S_ / 32, B_), 256>>>(
        h, hh, hT, S_, D_, SD, SD, SD);
    conv_and_transpose_kernel<<<dim3(F_ / 32, D_ / 32, 1), 256>>>(
        w1, nullptr, w1T, D_, F_, 0, 0, 0);
    conv_and_transpose_kernel<<<dim3(D_ / 32, F_ / 32, 1), 256>>>(
        w2, nullptr, w2T, F_, D_, 0, 0, 0);

    // 1) scores = (h @ h^T) / 32  (symmetric, fp16)
    mma_gemm_sym<<<dim3(NTRI, 1, B_), 128, DYN_SMEM>>>(
        hh, scores, D_, SD, SS, 0.03125f);

    // 2) softmax (+mask) -> fp16 probs
    softmax_kernel<<<B_ * S_, 256>>>(scores, mask, probs);

    // 3) attn = P @ h
    mma_gemm<0, float><<<dim3(D_ / 128, S_ / 128, B_), 128, DYN_SMEM>>>(
        probs, hT, nullptr, attn, S_, D_, S_, SS, SD, SD, 1.0f);

    // 4) h1 = LN1(h + attn)
    add_ln_kernel<<<B_ * S_, 256>>>(attn, h, g1, be1, h1, h1h);

    // 5) f1 = GELU(h1 @ w1 + b1)
    mma_gemm<1, __half><<<dim3(F_ / 128, (B_ * S_) / 128, 1), 128, DYN_SMEM>>>(
        h1h, w1T, b1, f1, B_ * S_, F_, D_, 0, 0, 0, 1.0f);

    // 6) f2 = f1 @ w2 + b2
    mma_gemm<2, float><<<dim3(D_ / 128, (B_ * S_) / 128, 1), 128, DYN_SMEM>>>(
        f1, w2T, b2, f2, B_ * S_, D_, F_, 0, 0, 0, 1.0f);

    // 7) out = LN2(h1 + f2)
    add_ln_kernel<<<B_ * S_, 256>>>(f2, h1, g2, be2, out, nullptr);
}